// round 8
// baseline (speedup 1.0000x reference)
#include <cuda_runtime.h>
#include <cuda_fp16.h>
#include <cstdint>

#define FEAT_IN   256
#define FEAT_OUT  64
#define MAX_N     100000
#define MAX_E     1600000
#define MAX_TOT   (MAX_E + MAX_N)
#define NEG_SLOPE 0.2f

// ---------------- scratch (device globals; no allocation allowed) ----------
__device__ __half g_hh[(size_t)MAX_N * FEAT_OUT];   // 12.8 MB fp16 h (gather-only)
__device__ float  g_asrc[MAX_N];
__device__ float  g_adst[MAX_N];
__device__ int    g_deg[MAX_N];
__device__ int    g_off[MAX_N];
__device__ int    g_cur[MAX_N];
__device__ int    g_adj[MAX_TOT];
__device__ int    g_counter;
__device__ int    g_is64;

// ---------------- dtype detection: int64 vs int32 edge_index ---------------
// int64 indices in [0, N) with N < 2^31 have every odd 32-bit word zero.
__global__ void detect_kernel(const unsigned int* __restrict__ w, int nwords) {
    __shared__ unsigned int sacc[256];
    int npairs = nwords >> 1;
    int stride = (npairs + 1023) / 1024;
    if (stride < 1) stride = 1;
    unsigned int acc = 0;
    for (int i = threadIdx.x; i < 1024; i += blockDim.x) {
        long long pi = (long long)i * stride;
        if (pi < npairs) acc |= w[2 * pi + 1];
    }
    sacc[threadIdx.x] = acc;
    __syncthreads();
    for (int s = 128; s > 0; s >>= 1) {
        if (threadIdx.x < s) sacc[threadIdx.x] |= sacc[threadIdx.x + s];
        __syncthreads();
    }
    if (threadIdx.x == 0) g_is64 = (sacc[0] == 0u) ? 1 : 0;
}

// ---------------- zero degrees + counter ------------------------------------
__global__ void zero_kernel(int N) {
    int i = blockIdx.x * blockDim.x + threadIdx.x;
    if (i < N) g_deg[i] = 0;
    if (i == 0) g_counter = 0;
}

// ---------------- CSR pass 1: histogram of dst -------------------------------
__global__ void count_kernel(const void* __restrict__ ei_raw, int E, int N) {
    int i = blockIdx.x * blockDim.x + threadIdx.x;
    int tot = E + N;
    if (i >= tot) return;
    int d;
    if (i < E) {
        if (g_is64) d = (int)((const unsigned int*)ei_raw)[2 * ((size_t)E + i)];
        else        d = ((const int*)ei_raw)[E + i];
    } else d = i - E;
    atomicAdd(&g_deg[d], 1);
}

// ---------------- CSR pass 2: contiguous (unordered) range assignment -------
// Block-exclusive-scan of degrees; one global atomic per block. Ranges are
// contiguous per dst (all the CSR gather needs) though not globally sorted.
__global__ void offset_kernel(int N) {
    __shared__ int wsum[8];
    __shared__ int sbase;
    int d = blockIdx.x * 256 + threadIdx.x;
    int lane = threadIdx.x & 31, warp = threadIdx.x >> 5;
    int v = (d < N) ? g_deg[d] : 0;
    int x = v;
#pragma unroll
    for (int o = 1; o < 32; o <<= 1) {
        int y = __shfl_up_sync(0xffffffffu, x, o);
        if (lane >= o) x += y;
    }
    if (lane == 31) wsum[warp] = x;
    __syncthreads();
    if (warp == 0) {
        int wv = (lane < 8) ? wsum[lane] : 0;
        int wx = wv;
#pragma unroll
        for (int o = 1; o < 8; o <<= 1) {
            int y = __shfl_up_sync(0xffffffffu, wx, o);
            if (lane >= o) wx += y;
        }
        if (lane < 8) wsum[lane] = wx - wv;      // exclusive warp offsets
        if (lane == 7) sbase = atomicAdd(&g_counter, wx);  // block total
    }
    __syncthreads();
    int off = sbase + wsum[warp] + (x - v);
    if (d < N) { g_off[d] = off; g_cur[d] = off; }
}

// ---------------- CSR pass 3: fill adjacency ---------------------------------
__global__ void fill_kernel(const void* __restrict__ ei_raw, int E, int N) {
    int i = blockIdx.x * blockDim.x + threadIdx.x;
    int tot = E + N;
    if (i >= tot) return;
    int s, d;
    if (i < E) {
        if (g_is64) {
            const unsigned int* w = (const unsigned int*)ei_raw;
            s = (int)w[2 * (size_t)i];
            d = (int)w[2 * ((size_t)E + i)];
        } else {
            const int* p = (const int*)ei_raw;
            s = p[i];
            d = p[E + i];
        }
    } else s = d = i - E;
    int pos = atomicAdd(&g_cur[d], 1);
    g_adj[pos] = s;
}

// ---------------- tf32 tensor-core GEMM + fused attention scores -----------
// h[N,64] = x[N,256] @ W[256,64];  a_src = h.att_src; a_dst = h.att_dst
// Register double-buffered; conflict-free smem fragment loads:
//   As stride 36 -> bank=(4g+q)%32 distinct; Bs transposed [n][k] stride 36.
#define BM 128
#define BK 32
#define BN 64
#define AS_STRIDE (BK + 4)

__device__ __forceinline__ uint32_t f2tf32(float f) {
    uint32_t u;
    asm("cvt.rna.tf32.f32 %0, %1;" : "=r"(u) : "f"(f));
    return u;
}

__global__ __launch_bounds__(256) void gemm_tf32_kernel(
    const float* __restrict__ x, const float* __restrict__ W,
    const float* __restrict__ att_src, const float* __restrict__ att_dst, int N) {
    __shared__ uint32_t As[BM][AS_STRIDE];
    __shared__ uint32_t Bs[BN][AS_STRIDE];     // transposed: Bs[n][k]
    __shared__ float sred[2][BM][2];

    const int t     = threadIdx.x;
    const int warp  = t >> 5, lane = t & 31;
    const int warpM = warp >> 1;
    const int warpN = warp & 1;
    const int g     = lane >> 2;
    const int q     = lane & 3;
    const int row0  = blockIdx.x * BM;

    const int bc  = t & 63;        // B staging: col
    const int br0 = t >> 6;        // B staging: k-row base (0..3)

    float c[2][4][4];
#pragma unroll
    for (int mt = 0; mt < 2; mt++)
#pragma unroll
        for (int nt = 0; nt < 4; nt++)
#pragma unroll
            for (int i = 0; i < 4; i++) c[mt][nt][i] = 0.0f;

    float4 ra[4];
    float  rbv[8];
    // ---- prefetch tile 0 ----
#pragma unroll
    for (int l = 0; l < 4; l++) {
        int idx = t + l * 256;
        int r = idx >> 3, cq = idx & 7;
        int nrow = row0 + r;
        ra[l] = make_float4(0.f, 0.f, 0.f, 0.f);
        if (nrow < N) ra[l] = *(const float4*)&x[(size_t)nrow * FEAT_IN + cq * 4];
    }
#pragma unroll
    for (int j = 0; j < 8; j++)
        rbv[j] = W[(size_t)(br0 + 4 * j) * FEAT_OUT + bc];

    for (int k0 = 0; k0 < FEAT_IN; k0 += BK) {
        // ---- store staged regs to smem (cvt to tf32) ----
#pragma unroll
        for (int l = 0; l < 4; l++) {
            int idx = t + l * 256;
            int r = idx >> 3, cq = idx & 7;
            uint4 u = make_uint4(f2tf32(ra[l].x), f2tf32(ra[l].y),
                                 f2tf32(ra[l].z), f2tf32(ra[l].w));
            *(uint4*)&As[r][cq * 4] = u;
        }
#pragma unroll
        for (int j = 0; j < 8; j++)
            Bs[bc][br0 + 4 * j] = f2tf32(rbv[j]);
        __syncthreads();

        // ---- prefetch next tile (overlaps with compute) ----
        if (k0 + BK < FEAT_IN) {
            int kn = k0 + BK;
#pragma unroll
            for (int l = 0; l < 4; l++) {
                int idx = t + l * 256;
                int r = idx >> 3, cq = idx & 7;
                int nrow = row0 + r;
                ra[l] = make_float4(0.f, 0.f, 0.f, 0.f);
                if (nrow < N) ra[l] = *(const float4*)&x[(size_t)nrow * FEAT_IN + kn + cq * 4];
            }
#pragma unroll
            for (int j = 0; j < 8; j++)
                rbv[j] = W[(size_t)(kn + br0 + 4 * j) * FEAT_OUT + bc];
        }

        // ---- compute ----
#pragma unroll
        for (int kk = 0; kk < BK; kk += 8) {
            uint32_t bf[4][2];
#pragma unroll
            for (int nt = 0; nt < 4; nt++) {
                int col = warpN * 32 + nt * 8 + g;
                bf[nt][0] = Bs[col][kk + q];
                bf[nt][1] = Bs[col][kk + q + 4];
            }
#pragma unroll
            for (int mt = 0; mt < 2; mt++) {
                int rbw = warpM * 32 + mt * 16;
                uint32_t a0 = As[rbw + g][kk + q];
                uint32_t a1 = As[rbw + g + 8][kk + q];
                uint32_t a2 = As[rbw + g][kk + q + 4];
                uint32_t a3 = As[rbw + g + 8][kk + q + 4];
#pragma unroll
                for (int nt = 0; nt < 4; nt++) {
                    asm volatile(
                        "mma.sync.aligned.m16n8k8.row.col.f32.tf32.tf32.f32 "
                        "{%0,%1,%2,%3}, {%4,%5,%6,%7}, {%8,%9}, {%0,%1,%2,%3};"
                        : "+f"(c[mt][nt][0]), "+f"(c[mt][nt][1]),
                          "+f"(c[mt][nt][2]), "+f"(c[mt][nt][3])
                        : "r"(a0), "r"(a1), "r"(a2), "r"(a3),
                          "r"(bf[nt][0]), "r"(bf[nt][1]));
                }
            }
        }
        __syncthreads();
    }

    // ---- epilogue: store h (fp16), compute per-row att scores (fp32) ----
    float a_s[4][2], a_d[4][2];
#pragma unroll
    for (int nt = 0; nt < 4; nt++) {
        int col = warpN * 32 + nt * 8 + 2 * q;
        a_s[nt][0] = att_src[col];     a_s[nt][1] = att_src[col + 1];
        a_d[nt][0] = att_dst[col];     a_d[nt][1] = att_dst[col + 1];
    }
    float vs[2][2] = {{0, 0}, {0, 0}};
    float vd[2][2] = {{0, 0}, {0, 0}};
#pragma unroll
    for (int mt = 0; mt < 2; mt++) {
        int rbase = row0 + warpM * 32 + mt * 16 + g;
#pragma unroll
        for (int nt = 0; nt < 4; nt++) {
            int col = warpN * 32 + nt * 8 + 2 * q;
            float c0 = c[mt][nt][0], c1 = c[mt][nt][1];
            float c2 = c[mt][nt][2], c3 = c[mt][nt][3];
            vs[mt][0] += c0 * a_s[nt][0] + c1 * a_s[nt][1];
            vd[mt][0] += c0 * a_d[nt][0] + c1 * a_d[nt][1];
            vs[mt][1] += c2 * a_s[nt][0] + c3 * a_s[nt][1];
            vd[mt][1] += c2 * a_d[nt][0] + c3 * a_d[nt][1];
            if (rbase < N)
                ((__half2*)(g_hh + (size_t)rbase * FEAT_OUT))[col >> 1] =
                    __float22half2_rn(make_float2(c0, c1));
            if (rbase + 8 < N)
                ((__half2*)(g_hh + (size_t)(rbase + 8) * FEAT_OUT))[col >> 1] =
                    __float22half2_rn(make_float2(c2, c3));
        }
    }
#pragma unroll
    for (int mt = 0; mt < 2; mt++)
#pragma unroll
        for (int hh = 0; hh < 2; hh++) {
#pragma unroll
            for (int o = 1; o < 4; o <<= 1) {
                vs[mt][hh] += __shfl_xor_sync(0xffffffffu, vs[mt][hh], o);
                vd[mt][hh] += __shfl_xor_sync(0xffffffffu, vd[mt][hh], o);
            }
        }
    if (q == 0) {
#pragma unroll
        for (int mt = 0; mt < 2; mt++) {
            int r = warpM * 32 + mt * 16 + g;
            sred[warpN][r][0] = vs[mt][0];
            sred[warpN][r][1] = vd[mt][0];
            sred[warpN][r + 8][0] = vs[mt][1];
            sred[warpN][r + 8][1] = vd[mt][1];
        }
    }
    __syncthreads();
    if (t < BM) {
        int nrow = row0 + t;
        if (nrow < N) {
            g_asrc[nrow] = sred[0][t][0] + sred[1][t][0];
            g_adst[nrow] = sred[0][t][1] + sred[1][t][1];
        }
    }
}

// ---------------- CSR gather: softmax-weighted aggregate + bias + L2-norm ---
// One warp per dst node. Pure reads + one clean store: no atomics at all.
__global__ __launch_bounds__(256) void gather_kernel(float* __restrict__ out,
                                                     const float* __restrict__ bias,
                                                     int N) {
    int gw = (blockIdx.x * blockDim.x + threadIdx.x) >> 5;
    int lane = threadIdx.x & 31;
    if (gw >= N) return;
    const int base = g_off[gw];
    const int deg  = g_deg[gw];
    const float ad = g_adst[gw];
    float accx = 0.f, accy = 0.f, den = 0.f;
    int e = 0;
    for (; e + 2 <= deg; e += 2) {                 // 2-way ILP for load latency
        int s0 = g_adj[base + e];
        int s1 = g_adj[base + e + 1];
        float a0 = g_asrc[s0];
        float a1 = g_asrc[s1];
        unsigned v0 = ((const unsigned*)g_hh)[(size_t)s0 * 32 + lane];
        unsigned v1 = ((const unsigned*)g_hh)[(size_t)s1 * 32 + lane];
        float t0 = a0 + ad; t0 = (t0 > 0.f) ? t0 : NEG_SLOPE * t0;
        float t1 = a1 + ad; t1 = (t1 > 0.f) ? t1 : NEG_SLOPE * t1;
        float w0 = __expf(t0);
        float w1 = __expf(t1);
        float2 f0 = __half22float2(*(__half2*)&v0);
        float2 f1 = __half22float2(*(__half2*)&v1);
        accx += w0 * f0.x; accy += w0 * f0.y;
        accx += w1 * f1.x; accy += w1 * f1.y;
        den  += w0 + w1;
    }
    if (e < deg) {
        int s0 = g_adj[base + e];
        float a0 = g_asrc[s0];
        unsigned v0 = ((const unsigned*)g_hh)[(size_t)s0 * 32 + lane];
        float t0 = a0 + ad; t0 = (t0 > 0.f) ? t0 : NEG_SLOPE * t0;
        float w0 = __expf(t0);
        float2 f0 = __half22float2(*(__half2*)&v0);
        accx += w0 * f0.x; accy += w0 * f0.y;
        den  += w0;
    }
    float rd = __fdividef(1.0f, den);
    float2 b = ((const float2*)bias)[lane];
    float ox = accx * rd + b.x;
    float oy = accy * rd + b.y;
    float ss = ox * ox + oy * oy;
#pragma unroll
    for (int o = 16; o > 0; o >>= 1) ss += __shfl_xor_sync(0xffffffffu, ss, o);
    float inv = 1.0f / fmaxf(sqrtf(ss), 1e-12f);
    ((float2*)out)[(size_t)gw * 32 + lane] = make_float2(ox * inv, oy * inv);
}

// ---------------- launch ----------------------------------------------------
extern "C" void kernel_launch(void* const* d_in, const int* in_sizes, int n_in,
                              void* d_out, int out_size) {
    const float* x       = (const float*)d_in[0];
    const void*  ei      = d_in[1];
    const float* W       = (const float*)d_in[2];
    const float* att_src = (const float*)d_in[3];
    const float* att_dst = (const float*)d_in[4];
    const float* bias    = (const float*)d_in[5];
    float*       out     = (float*)d_out;

    const int N   = in_sizes[0] / FEAT_IN;   // 100000
    const int E   = in_sizes[1] / 2;         // 1600000
    const int tot = E + N;

    detect_kernel<<<1, 256>>>((const unsigned int*)ei, 2 * E);
    zero_kernel<<<(N + 255) / 256, 256>>>(N);
    count_kernel<<<(tot + 255) / 256, 256>>>(ei, E, N);
    offset_kernel<<<(N + 255) / 256, 256>>>(N);
    fill_kernel<<<(tot + 255) / 256, 256>>>(ei, E, N);
    gemm_tf32_kernel<<<(N + BM - 1) / BM, 256>>>(x, W, att_src, att_dst, N);
    gather_kernel<<<(N + 7) / 8, 256>>>(out, bias, N);
}

// round 10
// speedup vs baseline: 1.3061x; 1.3061x over previous
#include <cuda_runtime.h>
#include <cuda_fp16.h>
#include <cstdint>

#define FEAT_IN   256
#define FEAT_OUT  64
#define MAX_N     100000
#define MAX_E     1600000
#define MAX_TOT   (MAX_E + MAX_N)
#define NEG_SLOPE 0.2f

// ---------------- scratch (device globals; no allocation allowed) ----------
__device__ __half g_hh[(size_t)MAX_N * FEAT_OUT];   // 12.8 MB fp16 h (gather-only)
__device__ float  g_asrc[MAX_N];
__device__ float  g_adst[MAX_N];
__device__ float  g_denom[MAX_N];
__device__ int    g_is64;

// ---------------- dtype detection: int64 vs int32 edge_index ---------------
// int64 indices in [0, N) with N < 2^31 have every odd 32-bit word zero.
__global__ void detect_kernel(const unsigned int* __restrict__ w, int nwords) {
    __shared__ unsigned int sacc[256];
    int npairs = nwords >> 1;
    int stride = (npairs + 1023) / 1024;
    if (stride < 1) stride = 1;
    unsigned int acc = 0;
    for (int i = threadIdx.x; i < 1024; i += blockDim.x) {
        long long pi = (long long)i * stride;
        if (pi < npairs) acc |= w[2 * pi + 1];
    }
    sacc[threadIdx.x] = acc;
    __syncthreads();
    for (int s = 128; s > 0; s >>= 1) {
        if (threadIdx.x < s) sacc[threadIdx.x] |= sacc[threadIdx.x + s];
        __syncthreads();
    }
    if (threadIdx.x == 0) g_is64 = (sacc[0] == 0u) ? 1 : 0;
}

// ---------------- zero out + denom -----------------------------------------
__global__ void zero_kernel(float* __restrict__ out, int n_out, int N) {
    int i = blockIdx.x * blockDim.x + threadIdx.x;
    if (i < n_out) out[i] = 0.0f;
    if (i < N) g_denom[i] = 0.0f;
}

// ---------------- tf32 tensor-core GEMM + fused attention scores -----------
// h[N,64] = x[N,256] @ W[256,64];  a_src = h.att_src; a_dst = h.att_dst
// Register double-buffered; conflict-free smem fragment loads:
//   As stride 36 -> bank=(4g+q)%32 distinct; Bs transposed [n][k] stride 36.
#define BM 128
#define BK 32
#define BN 64
#define AS_STRIDE (BK + 4)

__device__ __forceinline__ uint32_t f2tf32(float f) {
    uint32_t u;
    asm("cvt.rna.tf32.f32 %0, %1;" : "=r"(u) : "f"(f));
    return u;
}

__global__ __launch_bounds__(256) void gemm_tf32_kernel(
    const float* __restrict__ x, const float* __restrict__ W,
    const float* __restrict__ att_src, const float* __restrict__ att_dst, int N) {
    __shared__ uint32_t As[BM][AS_STRIDE];
    __shared__ uint32_t Bs[BN][AS_STRIDE];     // transposed: Bs[n][k]
    __shared__ float sred[2][BM][2];

    const int t     = threadIdx.x;
    const int warp  = t >> 5, lane = t & 31;
    const int warpM = warp >> 1;
    const int warpN = warp & 1;
    const int g     = lane >> 2;
    const int q     = lane & 3;
    const int row0  = blockIdx.x * BM;

    const int bc  = t & 63;        // B staging: col
    const int br0 = t >> 6;        // B staging: k-row base (0..3)

    float c[2][4][4];
#pragma unroll
    for (int mt = 0; mt < 2; mt++)
#pragma unroll
        for (int nt = 0; nt < 4; nt++)
#pragma unroll
            for (int i = 0; i < 4; i++) c[mt][nt][i] = 0.0f;

    float4 ra[4];
    float  rbv[8];
    // ---- prefetch tile 0 ----
#pragma unroll
    for (int l = 0; l < 4; l++) {
        int idx = t + l * 256;
        int r = idx >> 3, cq = idx & 7;
        int nrow = row0 + r;
        ra[l] = make_float4(0.f, 0.f, 0.f, 0.f);
        if (nrow < N) ra[l] = *(const float4*)&x[(size_t)nrow * FEAT_IN + cq * 4];
    }
#pragma unroll
    for (int j = 0; j < 8; j++)
        rbv[j] = W[(size_t)(br0 + 4 * j) * FEAT_OUT + bc];

    for (int k0 = 0; k0 < FEAT_IN; k0 += BK) {
        // ---- store staged regs to smem (cvt to tf32) ----
#pragma unroll
        for (int l = 0; l < 4; l++) {
            int idx = t + l * 256;
            int r = idx >> 3, cq = idx & 7;
            uint4 u = make_uint4(f2tf32(ra[l].x), f2tf32(ra[l].y),
                                 f2tf32(ra[l].z), f2tf32(ra[l].w));
            *(uint4*)&As[r][cq * 4] = u;
        }
#pragma unroll
        for (int j = 0; j < 8; j++)
            Bs[bc][br0 + 4 * j] = f2tf32(rbv[j]);
        __syncthreads();

        // ---- prefetch next tile (overlaps with compute) ----
        if (k0 + BK < FEAT_IN) {
            int kn = k0 + BK;
#pragma unroll
            for (int l = 0; l < 4; l++) {
                int idx = t + l * 256;
                int r = idx >> 3, cq = idx & 7;
                int nrow = row0 + r;
                ra[l] = make_float4(0.f, 0.f, 0.f, 0.f);
                if (nrow < N) ra[l] = *(const float4*)&x[(size_t)nrow * FEAT_IN + kn + cq * 4];
            }
#pragma unroll
            for (int j = 0; j < 8; j++)
                rbv[j] = W[(size_t)(kn + br0 + 4 * j) * FEAT_OUT + bc];
        }

        // ---- compute ----
#pragma unroll
        for (int kk = 0; kk < BK; kk += 8) {
            uint32_t bf[4][2];
#pragma unroll
            for (int nt = 0; nt < 4; nt++) {
                int col = warpN * 32 + nt * 8 + g;
                bf[nt][0] = Bs[col][kk + q];
                bf[nt][1] = Bs[col][kk + q + 4];
            }
#pragma unroll
            for (int mt = 0; mt < 2; mt++) {
                int rbw = warpM * 32 + mt * 16;
                uint32_t a0 = As[rbw + g][kk + q];
                uint32_t a1 = As[rbw + g + 8][kk + q];
                uint32_t a2 = As[rbw + g][kk + q + 4];
                uint32_t a3 = As[rbw + g + 8][kk + q + 4];
#pragma unroll
                for (int nt = 0; nt < 4; nt++) {
                    asm volatile(
                        "mma.sync.aligned.m16n8k8.row.col.f32.tf32.tf32.f32 "
                        "{%0,%1,%2,%3}, {%4,%5,%6,%7}, {%8,%9}, {%0,%1,%2,%3};"
                        : "+f"(c[mt][nt][0]), "+f"(c[mt][nt][1]),
                          "+f"(c[mt][nt][2]), "+f"(c[mt][nt][3])
                        : "r"(a0), "r"(a1), "r"(a2), "r"(a3),
                          "r"(bf[nt][0]), "r"(bf[nt][1]));
                }
            }
        }
        __syncthreads();
    }

    // ---- epilogue: store h (fp16), compute per-row att scores (fp32) ----
    float a_s[4][2], a_d[4][2];
#pragma unroll
    for (int nt = 0; nt < 4; nt++) {
        int col = warpN * 32 + nt * 8 + 2 * q;
        a_s[nt][0] = att_src[col];     a_s[nt][1] = att_src[col + 1];
        a_d[nt][0] = att_dst[col];     a_d[nt][1] = att_dst[col + 1];
    }
    float vs[2][2] = {{0, 0}, {0, 0}};
    float vd[2][2] = {{0, 0}, {0, 0}};
#pragma unroll
    for (int mt = 0; mt < 2; mt++) {
        int rbase = row0 + warpM * 32 + mt * 16 + g;
#pragma unroll
        for (int nt = 0; nt < 4; nt++) {
            int col = warpN * 32 + nt * 8 + 2 * q;
            float c0 = c[mt][nt][0], c1 = c[mt][nt][1];
            float c2 = c[mt][nt][2], c3 = c[mt][nt][3];
            vs[mt][0] += c0 * a_s[nt][0] + c1 * a_s[nt][1];
            vd[mt][0] += c0 * a_d[nt][0] + c1 * a_d[nt][1];
            vs[mt][1] += c2 * a_s[nt][0] + c3 * a_s[nt][1];
            vd[mt][1] += c2 * a_d[nt][0] + c3 * a_d[nt][1];
            if (rbase < N)
                ((__half2*)(g_hh + (size_t)rbase * FEAT_OUT))[col >> 1] =
                    __float22half2_rn(make_float2(c0, c1));
            if (rbase + 8 < N)
                ((__half2*)(g_hh + (size_t)(rbase + 8) * FEAT_OUT))[col >> 1] =
                    __float22half2_rn(make_float2(c2, c3));
        }
    }
#pragma unroll
    for (int mt = 0; mt < 2; mt++)
#pragma unroll
        for (int hh = 0; hh < 2; hh++) {
#pragma unroll
            for (int o = 1; o < 4; o <<= 1) {
                vs[mt][hh] += __shfl_xor_sync(0xffffffffu, vs[mt][hh], o);
                vd[mt][hh] += __shfl_xor_sync(0xffffffffu, vd[mt][hh], o);
            }
        }
    if (q == 0) {
#pragma unroll
        for (int mt = 0; mt < 2; mt++) {
            int r = warpM * 32 + mt * 16 + g;
            sred[warpN][r][0] = vs[mt][0];
            sred[warpN][r][1] = vd[mt][0];
            sred[warpN][r + 8][0] = vs[mt][1];
            sred[warpN][r + 8][1] = vd[mt][1];
        }
    }
    __syncthreads();
    if (t < BM) {
        int nrow = row0 + t;
        if (nrow < N) {
            g_asrc[nrow] = sred[0][t][0] + sred[1][t][0];
            g_adst[nrow] = sred[0][t][1] + sred[1][t][1];
        }
    }
}

// ---------------- fused edge pass: w, denom, UNNORMALIZED aggregate --------
// out[d] += w * h[s] (h gathered fp16); denom[d] += w.  Division deferred to
// norm_kernel.  (Measured 85.2us in R5 — within ~20% of the LTS RMW-op floor.)
__global__ __launch_bounds__(256) void edge_kernel(const void* __restrict__ ei_raw,
                                                   float* __restrict__ out,
                                                   int E, int N) {
    __shared__ int   ss[256], sd[256];
    __shared__ float sw[256];
    const int tot  = E + N;
    const int base = blockIdx.x * 256;
    const int i    = base + threadIdx.x;

    if (i < tot) {
        int s, d;
        if (i < E) {
            if (g_is64) {
                const long long* p = (const long long*)ei_raw;
                s = (int)p[i];
                d = (int)p[(size_t)E + i];
            } else {
                const int* p = (const int*)ei_raw;
                s = p[i];
                d = p[E + i];
            }
        } else {
            s = d = i - E;   // self loop
        }
        float e = g_asrc[s] + g_adst[d];
        e = (e > 0.f) ? e : NEG_SLOPE * e;
        float w = __expf(e);
        ss[threadIdx.x] = s;
        sd[threadIdx.x] = d;
        sw[threadIdx.x] = w;
        atomicAdd(&g_denom[d], w);
    }
    __syncthreads();

    const int warp = threadIdx.x >> 5, lane = threadIdx.x & 31;
    const int half = lane >> 4, li = lane & 15;     // 2 edges per warp per iter
    const int nblk = min(256, tot - base);
#pragma unroll 8
    for (int it = 0; it < 16; it++) {
        int e = warp * 32 + it * 2 + half;
        if (e < nblk) {
            int s = ss[e], d = sd[e];
            float w = sw[e];
            uint2 hv = ((const uint2*)(g_hh + (size_t)s * FEAT_OUT))[li];
            __half2* ph = (__half2*)&hv;
            float2 f01 = __half22float2(ph[0]);
            float2 f23 = __half22float2(ph[1]);
            float* p = out + (size_t)d * FEAT_OUT + li * 4;
            asm volatile("red.global.add.v4.f32 [%0], {%1, %2, %3, %4};"
                         :: "l"(p), "f"(w * f01.x), "f"(w * f01.y),
                            "f"(w * f23.x), "f"(w * f23.y) : "memory");
        }
    }
}

// ---------------- divide by denom, add bias, row-wise L2 normalize ---------
__global__ void norm_kernel(float* __restrict__ out, const float* __restrict__ bias, int N) {
    int gw = (blockIdx.x * blockDim.x + threadIdx.x) >> 5;
    int lane = threadIdx.x & 31;
    if (gw >= N) return;
    float rd = __fdividef(1.0f, g_denom[gw]);
    float2 v = ((float2*)out)[(size_t)gw * 32 + lane];
    float2 b = ((const float2*)bias)[lane];
    v.x = v.x * rd + b.x;
    v.y = v.y * rd + b.y;
    float ss = v.x * v.x + v.y * v.y;
#pragma unroll
    for (int o = 16; o > 0; o >>= 1) ss += __shfl_xor_sync(0xffffffffu, ss, o);
    float inv = 1.0f / fmaxf(sqrtf(ss), 1e-12f);
    v.x *= inv; v.y *= inv;
    ((float2*)out)[(size_t)gw * 32 + lane] = v;
}

// ---------------- launch ----------------------------------------------------
extern "C" void kernel_launch(void* const* d_in, const int* in_sizes, int n_in,
                              void* d_out, int out_size) {
    const float* x       = (const float*)d_in[0];
    const void*  ei      = d_in[1];
    const float* W       = (const float*)d_in[2];
    const float* att_src = (const float*)d_in[3];
    const float* att_dst = (const float*)d_in[4];
    const float* bias    = (const float*)d_in[5];
    float*       out     = (float*)d_out;

    const int N   = in_sizes[0] / FEAT_IN;   // 100000
    const int E   = in_sizes[1] / 2;         // 1600000
    const int tot = E + N;

    detect_kernel<<<1, 256>>>((const unsigned int*)ei, 2 * E);
    zero_kernel<<<(N * FEAT_OUT + 255) / 256, 256>>>(out, N * FEAT_OUT, N);
    gemm_tf32_kernel<<<(N + BM - 1) / BM, 256>>>(x, W, att_src, att_dst, N);
    edge_kernel<<<(tot + 255) / 256, 256>>>(ei, out, E, N);
    norm_kernel<<<(N + 7) / 8, 256>>>(out, bias, N);
}